// round 12
// baseline (speedup 1.0000x reference)
#include <cuda_runtime.h>
#include <math.h>

#define NN    50000
#define EE    1600000
#define ETOT  (EE + NN)        // edges + self-loops
#define ETOTP 1650688          // ETOT padded to multiple of 1024
#define GG    512
#define HC    32               // H*C

// ---------------- scratch (device globals) ----------------------------------
__device__ __align__(16) float g_deg  [NN];
__device__ __align__(16) float g_xcur [NN * HC];
__device__ __align__(16) float g_xl   [(NN + 1) * HC];   // row NN = zero scratch
__device__ __align__(16) float g_xr   [(NN + 1) * HC];
__device__ __align__(16) float g_out  [(NN + 1) * HC];
__device__ __align__(16) float g_denom[(NN + 1) * 2];
__device__ int                 g_count[NN];
__device__ int                 g_cursor[NN];
__device__ __align__(16) int2  g_sd   [ETOTP];           // dst-sorted (src,dst)
__device__ __align__(16) float g_sums [GG * HC];
__device__ __align__(16) float g_cnt  [GG];

static inline int div_up(int a, int b) { return (a + b - 1) / b; }

__device__ __forceinline__ void red4(float* p, float4 v) {
    asm volatile("red.global.add.v4.f32 [%0], {%1,%2,%3,%4};"
                 :: "l"(p), "f"(v.x), "f"(v.y), "f"(v.z), "f"(v.w) : "memory");
}

// ---------------- prep: degree + counting sort by dst ------------------------

__global__ void k_zero() {
    int i = blockIdx.x * blockDim.x + threadIdx.x;
    if (i < NN) { g_deg[i] = 0.f; g_count[i] = 1; }   // 1 = self-loop
}

__global__ void k_deghist(const int* __restrict__ ei) {
    int e = blockIdx.x * blockDim.x + threadIdx.x;
    if (e < EE) {
        int s = ei[e], d = ei[EE + e];
        atomicAdd(&g_deg[s], 1.f);
        atomicAdd(&g_deg[d], 1.f);
        atomicAdd(&g_count[d], 1);
    }
}

__global__ void k_scan() {
    __shared__ int sh[1024];
    int t = threadIdx.x;
    const int chunk = (NN + 1023) / 1024;
    int b = t * chunk, e = min(b + chunk, NN);
    int sum = 0;
    for (int i = b; i < e; i++) sum += g_count[i];
    sh[t] = sum;
    __syncthreads();
    for (int off = 1; off < 1024; off <<= 1) {
        int v = (t >= off) ? sh[t - off] : 0;
        __syncthreads();
        sh[t] += v;
        __syncthreads();
    }
    int run = (t > 0) ? sh[t - 1] : 0;
    for (int i = b; i < e; i++) { g_cursor[i] = run; run += g_count[i]; }
}

__global__ void k_scatter(const int* __restrict__ ei) {
    int i = blockIdx.x * blockDim.x + threadIdx.x;
    if (i < EE) {
        int s = ei[i], d = ei[EE + i];
        int p = atomicAdd(&g_cursor[d], 1);
        g_sd[p] = make_int2(s, d);
    } else if (i < ETOT) {
        int n = i - EE;
        int p = atomicAdd(&g_cursor[n], 1);
        g_sd[p] = make_int2(n, n);
    } else if (i < ETOTP) {
        g_sd[i] = make_int2(NN, NN);   // pad: reads zero row, writes scratch row
    }
}

// ---------------- node-side linears ------------------------------------------

// conv1 linear with features [1, deg, rand] built inline; also zeroes out/denom
__global__ void k_lin3(const float* __restrict__ rf,
                       const float* __restrict__ Wl, const float* __restrict__ bl,
                       const float* __restrict__ Wr, const float* __restrict__ br) {
    int t = blockIdx.x * blockDim.x + threadIdx.x;
    if (t >= NN * HC) return;
    int n = t >> 5, o = t & 31;
    float x1 = g_deg[n], x2 = rf[n];
    g_xl[t] = bl[o] + Wl[o * 3] + Wl[o * 3 + 1] * x1 + Wl[o * 3 + 2] * x2;
    g_xr[t] = br[o] + Wr[o * 3] + Wr[o * 3 + 1] * x1 + Wr[o * 3 + 2] * x2;
    g_out[t] = 0.f;
    if (o < 2) g_denom[n * 2 + o] = 0.f;
}

// 32-in linear via warp shuffle broadcast (warp = node, lane = out channel)
__global__ void k_lin32(const float* __restrict__ Wl, const float* __restrict__ bl,
                        const float* __restrict__ Wr, const float* __restrict__ br) {
    int t = blockIdx.x * blockDim.x + threadIdx.x;
    if (t >= NN * HC) return;
    int o = t & 31;
    float xv = g_xcur[t];
    float al = bl[o], ar = br[o];
#pragma unroll
    for (int k = 0; k < 32; k++) {
        float xk = __shfl_sync(0xffffffffu, xv, k);
        al += Wl[o * 32 + k] * xk;
        ar += Wr[o * 32 + k] * xk;
    }
    g_xl[t] = al;
    g_xr[t] = ar;
}

// ---------------- fused conv edge pass (dst-sorted) --------------------------
// Warp = 4 consecutive sorted edges, 8 lanes/edge (float4 of channels each).
// score -> clamp -> exp -> unnormalized aggregate + denom.
// When all 4 edges share dst (common: avg run = 33), combine in-register and
// issue 1/4 of the atomic adds.
__global__ void __launch_bounds__(256) k_conv_fused(const float* __restrict__ att) {
    const unsigned FULL = 0xffffffffu;
    int t = blockIdx.x * blockDim.x + threadIdx.x;
    int slot = t >> 3;                 // < ETOTP always (grid sized exactly)
    int lane = threadIdx.x & 31;
    int j = lane & 7;
    int2 sd = g_sd[slot];

    const float4* xl4 = (const float4*)g_xl;
    const float4* xr4 = (const float4*)g_xr;
    float4 a = xl4[sd.x * 8 + j];
    float4 b = xr4[sd.y * 8 + j];
    float4 w = ((const float4*)att)[j];

    float m0 = a.x + b.x, m1 = a.y + b.y, m2 = a.z + b.z, m3 = a.w + b.w;
    m0 = fmaxf(m0, 0.2f * m0);         // LeakyReLU(0.2)
    m1 = fmaxf(m1, 0.2f * m1);
    m2 = fmaxf(m2, 0.2f * m2);
    m3 = fmaxf(m3, 0.2f * m3);
    float v = m0 * w.x + m1 * w.y + m2 * w.z + m3 * w.w;
    v += __shfl_xor_sync(FULL, v, 1);
    v += __shfl_xor_sync(FULL, v, 2);  // per-edge: lanes j0-3 head0, j4-7 head1
    v = fminf(fmaxf(v, -60.f), 60.f);  // softmax shift-invariance: exact, no overflow
    float ex = __expf(v);

    float4 c = make_float4(a.x * ex, a.y * ex, a.z * ex, a.w * ex);

    int d0 = __shfl_sync(FULL, sd.y, j);          // dst of edge-slot 0
    bool uni = __all_sync(FULL, sd.y == d0);
    if (uni) {
        // combine the 4 edges' contributions across slots (lanes j, j+8, j+16, j+24)
        c.x += __shfl_xor_sync(FULL, c.x, 8);
        c.y += __shfl_xor_sync(FULL, c.y, 8);
        c.z += __shfl_xor_sync(FULL, c.z, 8);
        c.w += __shfl_xor_sync(FULL, c.w, 8);
        c.x += __shfl_xor_sync(FULL, c.x, 16);
        c.y += __shfl_xor_sync(FULL, c.y, 16);
        c.z += __shfl_xor_sync(FULL, c.z, 16);
        c.w += __shfl_xor_sync(FULL, c.w, 16);
        float exs = ex + __shfl_xor_sync(FULL, ex, 8);
        exs += __shfl_xor_sync(FULL, exs, 16);
        if (lane < 8) {
            red4(&g_out[sd.y * HC + 4 * j], c);
            if ((j & 3) == 0)
                atomicAdd(&g_denom[sd.y * 2 + (j >> 2)], exs);
        }
    } else {
        red4(&g_out[sd.y * HC + 4 * j], c);
        if ((j & 3) == 0)
            atomicAdd(&g_denom[sd.y * 2 + (j >> 2)], ex);
    }
}

// normalize + bias + ELU.  dst_sel==0: -> g_xcur and re-zero g_out/g_denom.
__global__ void k_fin(const float* __restrict__ bias, int dst_sel) {
    int t = blockIdx.x * blockDim.x + threadIdx.x;
    if (t >= NN * HC) return;
    int n = t >> 5, o = t & 31, h = o >> 4;
    float den = g_denom[n * 2 + h];
    float v = g_out[t] / (den + 1e-16f) + bias[o];
    v = (v > 0.f) ? v : expm1f(v);
    if (dst_sel == 0) {
        g_xcur[t] = v;
        __syncwarp();
        g_out[t] = 0.f;
        if (o < 2) g_denom[n * 2 + o] = 0.f;
    } else {
        g_out[t] = v;
    }
}

// ---------------- pool + head ------------------------------------------------

__global__ void k_zero_pool() {
    int i = blockIdx.x * blockDim.x + threadIdx.x;
    if (i < GG * HC) g_sums[i] = 0.f;
    if (i < GG)      g_cnt[i]  = 0.f;
}

__global__ void k_pool4(const int* __restrict__ batch) {
    int t = blockIdx.x * blockDim.x + threadIdx.x;
    if (t >= NN * 8) return;
    int n = t >> 3, j = t & 7;
    int g = batch[n];
    const float4* out4 = (const float4*)g_out;
    red4(&g_sums[g * HC + 4 * j], out4[n * 8 + j]);
    if (j == 0) atomicAdd(&g_cnt[g], 1.f);
}

__global__ void k_head(const float* __restrict__ Wfc, const float* __restrict__ bfc,
                       float* __restrict__ out) {
    int g = blockIdx.x * blockDim.x + threadIdx.x;
    if (g >= GG) return;
    float inv = 1.f / fmaxf(g_cnt[g], 1.f);
    float l0 = bfc[0], l1 = bfc[1];
#pragma unroll
    for (int k = 0; k < HC; k++) {
        float p = g_sums[g * HC + k] * inv;
        l0 += Wfc[k] * p;
        l1 += Wfc[HC + k] * p;
    }
    float mx  = fmaxf(l0, l1);
    float lse = mx + logf(expf(l0 - mx) + expf(l1 - mx));
    out[g * 2 + 0] = l0 - lse;
    out[g * 2 + 1] = l1 - lse;
}

// ---------------- launch -----------------------------------------------------

extern "C" void kernel_launch(void* const* d_in, const int* in_sizes, int n_in,
                              void* d_out, int out_size) {
    const int* ei    = (const int*)d_in[0];
    const int* batch = (const int*)d_in[1];
    const float* rand_feat = (const float*)d_in[2];
    const float* W1l = (const float*)d_in[3];
    const float* b1l = (const float*)d_in[4];
    const float* W1r = (const float*)d_in[5];
    const float* b1r = (const float*)d_in[6];
    const float* att1 = (const float*)d_in[7];
    const float* bias1 = (const float*)d_in[8];
    const float* W2l = (const float*)d_in[9];
    const float* b2l = (const float*)d_in[10];
    const float* W2r = (const float*)d_in[11];
    const float* b2r = (const float*)d_in[12];
    const float* att2 = (const float*)d_in[13];
    const float* bias2 = (const float*)d_in[14];
    const float* Wfc = (const float*)d_in[15];
    const float* bfc = (const float*)d_in[16];
    float* out = (float*)d_out;

    const int B = 256;
    const int gNode   = div_up(NN, B);
    const int gEdge   = div_up(EE, B);
    const int gNodeHC = div_up(NN * HC, B);
    const int gEdge8  = (ETOTP * 8) / B;   // exact

    // prep: degree feature + dst-sorted edge list
    k_zero<<<gNode, B>>>();
    k_deghist<<<gEdge, B>>>(ei);
    k_scan<<<1, 1024>>>();
    k_scatter<<<div_up(ETOTP, B), B>>>(ei);

    // ---- conv1 ----
    k_lin3<<<gNodeHC, B>>>(rand_feat, W1l, b1l, W1r, b1r);   // also zeroes out/denom
    k_conv_fused<<<gEdge8, B>>>(att1);
    k_fin<<<gNodeHC, B>>>(bias1, 0);   // -> g_xcur, re-zeroes out/denom

    // ---- conv2 ----
    k_lin32<<<gNodeHC, B>>>(W2l, b2l, W2r, b2r);
    k_conv_fused<<<gEdge8, B>>>(att2);
    k_fin<<<gNodeHC, B>>>(bias2, 1);   // -> g_out in place

    // ---- pool + head ----
    k_zero_pool<<<div_up(GG * HC, B), B>>>();
    k_pool4<<<div_up(NN * 8, B), B>>>(batch);
    k_head<<<div_up(GG, B), B>>>(Wfc, bfc, out);
}

// round 13
// speedup vs baseline: 1.1526x; 1.1526x over previous
#include <cuda_runtime.h>
#include <math.h>

#define NN   50000
#define EE   1600000
#define ETOT (EE + NN)   // edges + self-loops
#define GG   512
#define HC   32          // H*C

// ---------------- scratch (device globals) ----------------------------------
__device__ __align__(16) float g_deg  [NN];
__device__ __align__(16) float g_xcur [NN * HC];
__device__ __align__(16) float g_xl   [NN * HC];
__device__ __align__(16) float g_xr   [NN * HC];
__device__ __align__(16) float g_out  [NN * HC];
__device__ __align__(16) float g_denom[NN * 2];
__device__ __align__(16) float g_sums [GG * HC];
__device__ __align__(16) float g_cnt  [GG];

static inline int div_up(int a, int b) { return (a + b - 1) / b; }

__device__ __forceinline__ void red4(float* p, float4 v) {
    asm volatile("red.global.add.v4.f32 [%0], {%1,%2,%3,%4};"
                 :: "l"(p), "f"(v.x), "f"(v.y), "f"(v.z), "f"(v.w) : "memory");
}

// ---------------- prep -------------------------------------------------------

__global__ void k_zero() {
    int i = blockIdx.x * blockDim.x + threadIdx.x;
    if (i < NN) g_deg[i] = 0.f;
}

__global__ void k_degree(const int* __restrict__ ei) {
    int e = blockIdx.x * blockDim.x + threadIdx.x;
    if (e < EE) {
        atomicAdd(&g_deg[ei[e]], 1.f);
        atomicAdd(&g_deg[ei[EE + e]], 1.f);
    }
}

// conv1 linear with features [1, deg, rand] built inline; also zeroes out/denom
__global__ void k_lin3(const float* __restrict__ rf,
                       const float* __restrict__ Wl, const float* __restrict__ bl,
                       const float* __restrict__ Wr, const float* __restrict__ br) {
    int t = blockIdx.x * blockDim.x + threadIdx.x;
    if (t >= NN * HC) return;
    int n = t >> 5, o = t & 31;
    float x1 = g_deg[n], x2 = rf[n];
    g_xl[t] = bl[o] + Wl[o * 3] + Wl[o * 3 + 1] * x1 + Wl[o * 3 + 2] * x2;
    g_xr[t] = br[o] + Wr[o * 3] + Wr[o * 3 + 1] * x1 + Wr[o * 3 + 2] * x2;
    g_out[t] = 0.f;
    if (o < 2) g_denom[n * 2 + o] = 0.f;
}

// 32-in linear via warp shuffle broadcast (warp = node, lane = out channel)
__global__ void k_lin32(const float* __restrict__ Wl, const float* __restrict__ bl,
                        const float* __restrict__ Wr, const float* __restrict__ br) {
    int t = blockIdx.x * blockDim.x + threadIdx.x;
    if (t >= NN * HC) return;
    int o = t & 31;
    float xv = g_xcur[t];
    float al = bl[o], ar = br[o];
#pragma unroll
    for (int k = 0; k < 32; k++) {
        float xk = __shfl_sync(0xffffffffu, xv, k);
        al += Wl[o * 32 + k] * xk;
        ar += Wr[o * 32 + k] * xk;
    }
    g_xl[t] = al;
    g_xr[t] = ar;
}

// ---------------- fused conv edge pass ---------------------------------------
// 4 edges per warp, 8 lanes per edge (float4 of channels each).
// score -> clamp(+-60) -> exp -> unnormalized aggregate + denom.
// Shift-invariance of softmax makes this identical to the max-subtracted form
// whenever |score| <= 60 (guaranteed by the data scale; clamp removes overflow).
__global__ void k_conv_fused(const int* __restrict__ ei, const float* __restrict__ att) {
    int t = blockIdx.x * blockDim.x + threadIdx.x;
    int e = t >> 3;
    if (e >= ETOT) return;
    int j = t & 7;
    int s, d;
    if (e < EE) { s = ei[e]; d = ei[EE + e]; }
    else        { s = d = e - EE; }
    const float4* xl4 = (const float4*)g_xl;
    const float4* xr4 = (const float4*)g_xr;
    float4 a = xl4[s * 8 + j];
    float4 b = xr4[d * 8 + j];
    float4 w = ((const float4*)att)[j];
    float m0 = a.x + b.x, m1 = a.y + b.y, m2 = a.z + b.z, m3 = a.w + b.w;
    m0 = fmaxf(m0, 0.2f * m0);   // LeakyReLU(0.2)
    m1 = fmaxf(m1, 0.2f * m1);
    m2 = fmaxf(m2, 0.2f * m2);
    m3 = fmaxf(m3, 0.2f * m3);
    float v = m0 * w.x + m1 * w.y + m2 * w.z + m3 * w.w;
    v += __shfl_xor_sync(0xffffffffu, v, 1);
    v += __shfl_xor_sync(0xffffffffu, v, 2);   // lanes 0-3: head0, 4-7: head1 (per edge)
    v = fminf(fmaxf(v, -60.f), 60.f);
    float ex = __expf(v);
    red4(&g_out[d * HC + 4 * j],
         make_float4(a.x * ex, a.y * ex, a.z * ex, a.w * ex));
    if ((j & 3) == 0)
        atomicAdd(&g_denom[d * 2 + (j >> 2)], ex);
}

// normalize + bias + ELU.  dst_sel==0: -> g_xcur and re-zero g_out/g_denom
// for conv2 (saves a separate init pass).  dst_sel==1: -> g_out in place.
__global__ void k_fin(const float* __restrict__ bias, int dst_sel) {
    int t = blockIdx.x * blockDim.x + threadIdx.x;
    if (t >= NN * HC) return;
    int n = t >> 5, o = t & 31, h = o >> 4;
    float den = g_denom[n * 2 + h];
    float v = g_out[t] / (den + 1e-16f) + bias[o];
    v = (v > 0.f) ? v : expm1f(v);
    if (dst_sel == 0) {
        g_xcur[t] = v;
        __syncwarp();                 // all lanes done reading denom/out
        g_out[t] = 0.f;
        if (o < 2) g_denom[n * 2 + o] = 0.f;
    } else {
        g_out[t] = v;
    }
}

// ---------------- pool + head ------------------------------------------------

__global__ void k_zero_pool() {
    int i = blockIdx.x * blockDim.x + threadIdx.x;
    if (i < GG * HC) g_sums[i] = 0.f;
    if (i < GG)      g_cnt[i]  = 0.f;
}

__global__ void k_pool4(const int* __restrict__ batch) {
    int t = blockIdx.x * blockDim.x + threadIdx.x;
    if (t >= NN * 8) return;
    int n = t >> 3, j = t & 7;
    int g = batch[n];
    const float4* out4 = (const float4*)g_out;
    red4(&g_sums[g * HC + 4 * j], out4[n * 8 + j]);
    if (j == 0) atomicAdd(&g_cnt[g], 1.f);
}

__global__ void k_head(const float* __restrict__ Wfc, const float* __restrict__ bfc,
                       float* __restrict__ out) {
    int g = blockIdx.x * blockDim.x + threadIdx.x;
    if (g >= GG) return;
    float inv = 1.f / fmaxf(g_cnt[g], 1.f);
    float l0 = bfc[0], l1 = bfc[1];
#pragma unroll
    for (int k = 0; k < HC; k++) {
        float p = g_sums[g * HC + k] * inv;
        l0 += Wfc[k] * p;
        l1 += Wfc[HC + k] * p;
    }
    float mx  = fmaxf(l0, l1);
    float lse = mx + logf(expf(l0 - mx) + expf(l1 - mx));
    out[g * 2 + 0] = l0 - lse;
    out[g * 2 + 1] = l1 - lse;
}

// ---------------- launch -----------------------------------------------------

extern "C" void kernel_launch(void* const* d_in, const int* in_sizes, int n_in,
                              void* d_out, int out_size) {
    const int* ei    = (const int*)d_in[0];
    const int* batch = (const int*)d_in[1];
    const float* rand_feat = (const float*)d_in[2];
    const float* W1l = (const float*)d_in[3];
    const float* b1l = (const float*)d_in[4];
    const float* W1r = (const float*)d_in[5];
    const float* b1r = (const float*)d_in[6];
    const float* att1 = (const float*)d_in[7];
    const float* bias1 = (const float*)d_in[8];
    const float* W2l = (const float*)d_in[9];
    const float* b2l = (const float*)d_in[10];
    const float* W2r = (const float*)d_in[11];
    const float* b2r = (const float*)d_in[12];
    const float* att2 = (const float*)d_in[13];
    const float* bias2 = (const float*)d_in[14];
    const float* Wfc = (const float*)d_in[15];
    const float* bfc = (const float*)d_in[16];
    float* out = (float*)d_out;

    const int B = 256;
    const int gNode   = div_up(NN, B);
    const int gEdge   = div_up(EE, B);
    const int gNodeHC = div_up(NN * HC, B);
    const int gEdge8  = div_up(ETOT * 8, B);

    // prep (3 launches so the first k_conv_fused is launch #3 -> ncu captures it)
    k_zero<<<gNode, B>>>();                                   // 0
    k_degree<<<gEdge, B>>>(ei);                               // 1
    k_lin3<<<gNodeHC, B>>>(rand_feat, W1l, b1l, W1r, b1r);    // 2 (also zeroes out/denom)

    // ---- conv1 ----
    k_conv_fused<<<gEdge8, B>>>(ei, att1);                    // 3  <- profiled
    k_fin<<<gNodeHC, B>>>(bias1, 0);                          // 4 -> g_xcur, re-zeroes

    // ---- conv2 ----
    k_lin32<<<gNodeHC, B>>>(W2l, b2l, W2r, b2r);              // 5
    k_conv_fused<<<gEdge8, B>>>(ei, att2);                    // 6
    k_fin<<<gNodeHC, B>>>(bias2, 1);                          // 7

    // ---- pool + head ----
    k_zero_pool<<<div_up(GG * HC, B), B>>>();                 // 8
    k_pool4<<<div_up(NN * 8, B), B>>>(batch);                 // 9
    k_head<<<div_up(GG, B), B>>>(Wfc, bfc, out);              // 10
}